// round 16
// baseline (speedup 1.0000x reference)
#include <cuda_runtime.h>
#include <cuda_bf16.h>
#include <mma.h>
#include <math.h>
#include <stdint.h>

using namespace nvcuda;

#define Bq   8
#define Tq   1024
#define Dq   768
#define NEq  8
#define DSq  128
#define ROWS (Bq*Tq)            // 8192
#define SROWS (Bq*Tq*NEq)       // 65536

#define POOLED_OFF  0ll
#define MEM_OFF     6291456ll
#define STATE_OFF   56623104ll
#define HOLDER_OFF  65011712ll
#define TAGGED_OFF  65077248ll
#define VISIBLE_OFF 65142784ll
#define RW_OFF      65208320ll

// ---------------------------------------------------------------------------
// Scratch
// ---------------------------------------------------------------------------
__device__ __align__(16) __nv_bfloat16 g_hseq_hi[ROWS*Dq],    g_hseq_lo[ROWS*Dq];
__device__ __align__(16) __nv_bfloat16 g_state_hi[SROWS*DSq], g_state_lo[SROWS*DSq];
__device__ __align__(16) __nv_bfloat16 g_projh[ROWS*DSq],     g_projl[ROWS*DSq];
__device__ __align__(16) __nv_bfloat16 g_Ws_hi[Dq*NEq*Dq],    g_Ws_lo[Dq*NEq*Dq];
__device__ __align__(16) __nv_bfloat16 g_Wi_hi[DSq*Dq],       g_Wi_lo[DSq*Dq];
__device__ __align__(16) __nv_bfloat16 g_Wih_hi[3*DSq*DSq],   g_Wih_lo[3*DSq*DSq];
__device__ __align__(16) __nv_bfloat16 g_Wm_hi[Dq*DSq],       g_Wm_lo[Dq*DSq];
__device__ __align__(16) __nv_bfloat16 g_WmT_hi[DSq*Dq],      g_WmT_lo[DSq*Dq];
__device__ __align__(16) __nv_bfloat16 g_Mc_hi[Dq*NEq*DSq],   g_Mc_lo[Dq*NEq*DSq];
__device__ __align__(16) __nv_bfloat16 g_W1_hi[256*DSq],      g_W1_lo[256*DSq];
__device__ __align__(16) float g_Q[ROWS*3*DSq];
__device__ __align__(16) float g_pbias[Dq];
__device__ __align__(16) float g_b1cat[256];
__device__ __align__(16) float g_W2cat[256];
__device__ int g_prog[256];    // [0..127]: scan chunks; [128..191]: Q chunks

// ---------------------------------------------------------------------------
// helpers
// ---------------------------------------------------------------------------
__device__ __forceinline__ unsigned long long fma_f32x2(unsigned long long a, unsigned long long b, unsigned long long c) {
    unsigned long long d;
    asm("fma.rn.f32x2 %0, %1, %2, %3;" : "=l"(d) : "l"(a), "l"(b), "l"(c));
    return d;
}
__device__ __forceinline__ float lo_f(unsigned long long v) { return __uint_as_float((uint32_t)v); }
__device__ __forceinline__ float hi_f(unsigned long long v) { return __uint_as_float((uint32_t)(v >> 32)); }

__device__ __forceinline__ uint32_t smem_u32(const void* p) {
    uint32_t a;
    asm("{ .reg .u64 t; cvta.to.shared.u64 t, %1; cvt.u32.u64 %0, t; }" : "=r"(a) : "l"(p));
    return a;
}
#define CP_COMMIT() asm volatile("cp.async.commit_group;" ::: "memory")
#define CP_WAIT0()  asm volatile("cp.async.wait_group 0;" ::: "memory")
#define CP_WAIT1()  asm volatile("cp.async.wait_group 1;" ::: "memory")

__device__ __forceinline__ void cp16(uint32_t d, const void* s) {
    asm volatile("cp.async.cg.shared.global [%0], [%1], 16;" :: "r"(d), "l"(s));
}

__device__ __forceinline__ void hilo(float v, __nv_bfloat16& h, __nv_bfloat16& l) {
    h = __float2bfloat16(v);
    l = __float2bfloat16(v - __bfloat162float(h));
}

__device__ __forceinline__ float gelu_exact(float x) {
    return 0.5f * x * (1.0f + erff(x * 0.70710678118654752f));
}

// ---------------------------------------------------------------------------
// GEMM tiling constants
// ---------------------------------------------------------------------------
#define BKT    64
#define LDSK   72
#define E_ALO  9216
#define E_BHI  18432
#define E_BLO  27648
#define E_BUF  36864
#define TILE_B 18432
#define BUF_B  73728
#define SM_BYTES 147456

__device__ __forceinline__ void stage_async(uint32_t sdst, const __nv_bfloat16* __restrict__ g,
                                            long long row0, int k0, int ld, int tid)
{
#pragma unroll
    for (int it = 0; it < 2; it++) {
        int flat = it * 512 + tid;
        int row = flat >> 3, q = flat & 7;
        cp16(sdst + row * (LDSK * 2) + q * 16, g + (row0 + row) * (long long)ld + k0 + q * 8);
    }
}

__device__ __forceinline__ void stage4(uint32_t bufb,
                                       const __nv_bfloat16* Ahi, const __nv_bfloat16* Alo,
                                       const __nv_bfloat16* Bhi, const __nv_bfloat16* Blo,
                                       long long m0, int n0, int ka, int kb, int lda, int ldb, int tid)
{
    stage_async(bufb,              Ahi, m0, ka, lda, tid);
    stage_async(bufb + TILE_B,     Alo, m0, ka, lda, tid);
    stage_async(bufb + 2 * TILE_B, Bhi, n0, kb, ldb, tid);
    stage_async(bufb + 3 * TILE_B, Blo, n0, kb, ldb, tid);
    CP_COMMIT();
}

// 16-warp, 128x128 body (proj / Mc)
__device__ __forceinline__ void gemm128_body(
    char* smem, uint32_t sb, int tid,
    const __nv_bfloat16* __restrict__ Ahi, const __nv_bfloat16* __restrict__ Alo, int lda, int aK0,
    const __nv_bfloat16* __restrict__ Bhi, const __nv_bfloat16* __restrict__ Blo, int ldb,
    long long m0, int n0, int cOff,
    float* __restrict__ C, int ldc,
    const float* __restrict__ bias, int nChunks,
    __nv_bfloat16* __restrict__ outH, __nv_bfloat16* __restrict__ outL)
{
    __nv_bfloat16* s16 = reinterpret_cast<__nv_bfloat16*>(smem);
    const int wid = tid >> 5;
    const int wy = wid >> 2, wx = wid & 3;

    wmma::fragment<wmma::accumulator, 16, 16, 16, float> acc[2][2];
#pragma unroll
    for (int i = 0; i < 2; i++)
#pragma unroll
        for (int j = 0; j < 2; j++) wmma::fill_fragment(acc[i][j], 0.0f);

    stage4(sb, Ahi, Alo, Bhi, Blo, m0, n0, aK0, 0, lda, ldb, tid);

    for (int c = 0; c < nChunks; c++) {
        if (c + 1 < nChunks) {
            stage4(sb + ((c + 1) & 1) * BUF_B, Ahi, Alo, Bhi, Blo, m0, n0,
                   aK0 + (c + 1) * BKT, (c + 1) * BKT, lda, ldb, tid);
            CP_WAIT1();
        } else {
            CP_WAIT0();
        }
        __syncthreads();
        const __nv_bfloat16* base = s16 + (c & 1) * E_BUF;
#pragma unroll
        for (int ks = 0; ks < BKT; ks += 16) {
            wmma::fragment<wmma::matrix_b, 16, 16, 16, __nv_bfloat16, wmma::col_major> bh[2], bl[2];
            wmma::fragment<wmma::matrix_a, 16, 16, 16, __nv_bfloat16, wmma::row_major> ah[2], al[2];
#pragma unroll
            for (int fn = 0; fn < 2; fn++) {
                const int nb = wx * 32 + fn * 16;
                wmma::load_matrix_sync(bh[fn], base + E_BHI + nb * LDSK + ks, LDSK);
                wmma::load_matrix_sync(bl[fn], base + E_BLO + nb * LDSK + ks, LDSK);
            }
#pragma unroll
            for (int fm = 0; fm < 2; fm++) {
                const int mb = wy * 32 + fm * 16;
                wmma::load_matrix_sync(ah[fm], base + mb * LDSK + ks, LDSK);
                wmma::load_matrix_sync(al[fm], base + E_ALO + mb * LDSK + ks, LDSK);
            }
#pragma unroll
            for (int fm = 0; fm < 2; fm++)
#pragma unroll
                for (int fn = 0; fn < 2; fn++)
                    wmma::mma_sync(acc[fm][fn], ah[fm], bh[fn], acc[fm][fn]);
#pragma unroll
            for (int fm = 0; fm < 2; fm++)
#pragma unroll
                for (int fn = 0; fn < 2; fn++)
                    wmma::mma_sync(acc[fm][fn], ah[fm], bl[fn], acc[fm][fn]);
#pragma unroll
            for (int fm = 0; fm < 2; fm++)
#pragma unroll
                for (int fn = 0; fn < 2; fn++)
                    wmma::mma_sync(acc[fm][fn], al[fm], bh[fn], acc[fm][fn]);
        }
        __syncthreads();
    }

    float* Cs = reinterpret_cast<float*>(smem);
#pragma unroll
    for (int fm = 0; fm < 2; fm++)
#pragma unroll
        for (int fn = 0; fn < 2; fn++)
            wmma::store_matrix_sync(Cs + (wy * 32 + fm * 16) * 128 + wx * 32 + fn * 16,
                                    acc[fm][fn], 128, wmma::mem_row_major);
    __syncthreads();
#pragma unroll
    for (int it = 0; it < 8; it++) {
        int flat = it * 512 + tid;
        int row = flat >> 5, q = flat & 31;
        float4 v = *reinterpret_cast<const float4*>(Cs + row * 128 + q * 4);
        if (bias) {
            const float4 bv = *reinterpret_cast<const float4*>(bias + n0 + q * 4);
            v.x += bv.x; v.y += bv.y; v.z += bv.z; v.w += bv.w;
        }
        size_t co = (size_t)(m0 + row) * ldc + cOff + q * 4;
        if (C) *reinterpret_cast<float4*>(C + co) = v;
        if (outH) {
            __nv_bfloat16 h0,l0,h1,l1,h2,l2,h3,l3;
            hilo(v.x,h0,l0); hilo(v.y,h1,l1); hilo(v.z,h2,l2); hilo(v.w,h3,l3);
            __nv_bfloat162 ph0 = {h0,h1}, ph1 = {h2,h3}, pl0 = {l0,l1}, pl1 = {l2,l3};
            *reinterpret_cast<__nv_bfloat162*>(outH + co)     = ph0;
            *reinterpret_cast<__nv_bfloat162*>(outH + co + 2) = ph1;
            *reinterpret_cast<__nv_bfloat162*>(outL + co)     = pl0;
            *reinterpret_cast<__nv_bfloat162*>(outL + co + 2) = pl1;
        }
    }
}

// ---------------------------------------------------------------------------
// proj + Mc combined GEMM (112 blocks)
// ---------------------------------------------------------------------------
__global__ __launch_bounds__(512, 1)
void gemm_proj_mc(const __nv_bfloat16* __restrict__ hseqh, const __nv_bfloat16* __restrict__ hseql,
                  const __nv_bfloat16* __restrict__ Wih, const __nv_bfloat16* __restrict__ Wil,
                  const float* __restrict__ bi,
                  __nv_bfloat16* __restrict__ projh, __nv_bfloat16* __restrict__ projl,
                  const __nv_bfloat16* __restrict__ Wsh, const __nv_bfloat16* __restrict__ Wsl,
                  const __nv_bfloat16* __restrict__ WmTh, const __nv_bfloat16* __restrict__ WmTl,
                  __nv_bfloat16* __restrict__ Mch, __nv_bfloat16* __restrict__ Mcl)
{
    extern __shared__ __align__(16) char smem[];
    const int bid = blockIdx.x;
    if (bid < 64) {
        gemm128_body(smem, smem_u32(smem), threadIdx.x,
                     hseqh, hseql, Dq, 0, Wih, Wil, Dq,
                     (long long)bid * 128, 0, 0,
                     nullptr, DSq, bi, Dq / BKT, projh, projl);
    } else {
        const int idx = bid - 64;
        const int m = idx >> 3, e = idx & 7;
        gemm128_body(smem, smem_u32(smem), threadIdx.x,
                     Wsh, Wsl, NEq * Dq, e * Dq, WmTh, WmTl, Dq,
                     (long long)m * 128, 0, e * DSq,
                     nullptr, NEq * DSq, nullptr, Dq / BKT, Mch, Mcl);
    }
}

// ---------------------------------------------------------------------------
// FUSED kernel: 384 threads.
//  Blocks 0..63    : GRU scan (gated on Q flags, count 2 per 128-step chunk)
//  Blocks 64..191  : Q producer tiles 128x192 (chunk-major)
//  Blocks 192+     : consumers (128x192 tiles), r-pair interleave:
//     pair = g/11; rem = g%11; rem<5 -> r=2*pair,s=rem ; else r=2*pair+1,s=rem-5
//     s<4 memory, s==4 heads, s==5 pooled(p=pair)
// ---------------------------------------------------------------------------
#define G_TA_B  18432             // A tile bytes
#define G_EBHI  18432             // Bhi elem offset (after A hi+lo)
#define G_EBLO  32256             // Blo elem offset
#define G_EBUF  46080             // elems per buffer
#define G_BUF_B 92160             // bytes per buffer
#define F_SM    184320

__device__ __forceinline__ void f_stageA(uint32_t sdst, const __nv_bfloat16* __restrict__ g,
                                         long long row0, int k0, int ld, int tid)
{
#pragma unroll
    for (int it = 0; it < 3; it++) {
        int u = it * 384 + tid;
        if (u < 1024) {
            int row = u >> 3, q = u & 7;
            cp16(sdst + row * (LDSK * 2) + q * 16, g + (row0 + row) * (long long)ld + k0 + q * 8);
        }
    }
}
__device__ __forceinline__ void f_stageB192g(uint32_t sdst, const __nv_bfloat16* __restrict__ g,
                                             int n0, int k0, int ld, int tid)
{
#pragma unroll
    for (int it = 0; it < 4; it++) {
        int u = it * 384 + tid;
        int row = u >> 3, q = u & 7;
        cp16(sdst + row * (LDSK * 2) + q * 16, g + (size_t)(n0 + row) * ld + k0 + q * 8);
    }
}

__device__ __forceinline__ void f_stage192(uint32_t bufb,
                                           const __nv_bfloat16* Ahi, const __nv_bfloat16* Alo, long long row0, int lda,
                                           const __nv_bfloat16* Bhi, const __nv_bfloat16* Blo, int n0, int ldb,
                                           int k0, int tid)
{
    f_stageA(bufb,          Ahi, row0, k0, lda, tid);
    f_stageA(bufb + G_TA_B, Alo, row0, k0, lda, tid);
    f_stageB192g(bufb + G_EBHI * 2, Bhi, n0, k0, ldb, tid);
    f_stageB192g(bufb + G_EBLO * 2, Blo, n0, k0, ldb, tid);
    CP_COMMIT();
}

// 12-warp 128x192 mainloop; leaves fp32 C tile (ld 192) in smem.
__device__ __forceinline__ void f_loop192(char* smem, uint32_t sb, int tid,
                                          const __nv_bfloat16* Ahi, const __nv_bfloat16* Alo, long long row0, int lda,
                                          const __nv_bfloat16* Bhi, const __nv_bfloat16* Blo, int n0, int ldb,
                                          int nCh)
{
    __nv_bfloat16* s16 = reinterpret_cast<__nv_bfloat16*>(smem);
    const int wid = tid >> 5;
    const int wy = wid & 3;            // 4 row-groups of 32
    const int wx = wid >> 2;           // 3 col-groups of 64

    wmma::fragment<wmma::accumulator, 16, 16, 16, float> acc[2][4];
#pragma unroll
    for (int i = 0; i < 2; i++)
#pragma unroll
        for (int jj = 0; jj < 4; jj++) wmma::fill_fragment(acc[i][jj], 0.0f);

    f_stage192(sb, Ahi, Alo, row0, lda, Bhi, Blo, n0, ldb, 0, tid);

    for (int c = 0; c < nCh; c++) {
        if (c + 1 < nCh) {
            f_stage192(sb + ((c + 1) & 1) * G_BUF_B, Ahi, Alo, row0, lda,
                       Bhi, Blo, n0, ldb, (c + 1) * BKT, tid);
            CP_WAIT1();
        } else {
            CP_WAIT0();
        }
        __syncthreads();
        const __nv_bfloat16* base = s16 + (c & 1) * G_EBUF;
#pragma unroll
        for (int ks = 0; ks < BKT; ks += 16) {
            wmma::fragment<wmma::matrix_b, 16, 16, 16, __nv_bfloat16, wmma::col_major> bh[4], bl[4];
            wmma::fragment<wmma::matrix_a, 16, 16, 16, __nv_bfloat16, wmma::row_major> ah[2], al[2];
#pragma unroll
            for (int fn = 0; fn < 4; fn++) {
                const int nb = wx * 64 + fn * 16;
                wmma::load_matrix_sync(bh[fn], base + G_EBHI + nb * LDSK + ks, LDSK);
                wmma::load_matrix_sync(bl[fn], base + G_EBLO + nb * LDSK + ks, LDSK);
            }
#pragma unroll
            for (int fm = 0; fm < 2; fm++) {
                const int mb = wy * 32 + fm * 16;
                wmma::load_matrix_sync(ah[fm], base + mb * LDSK + ks, LDSK);
                wmma::load_matrix_sync(al[fm], base + 9216 + mb * LDSK + ks, LDSK);
            }
#pragma unroll
            for (int fm = 0; fm < 2; fm++)
#pragma unroll
                for (int fn = 0; fn < 4; fn++)
                    wmma::mma_sync(acc[fm][fn], ah[fm], bh[fn], acc[fm][fn]);
#pragma unroll
            for (int fm = 0; fm < 2; fm++)
#pragma unroll
                for (int fn = 0; fn < 4; fn++)
                    wmma::mma_sync(acc[fm][fn], ah[fm], bl[fn], acc[fm][fn]);
#pragma unroll
            for (int fm = 0; fm < 2; fm++)
#pragma unroll
                for (int fn = 0; fn < 4; fn++)
                    wmma::mma_sync(acc[fm][fn], al[fm], bh[fn], acc[fm][fn]);
        }
        __syncthreads();
    }

    float* Cs = reinterpret_cast<float*>(smem);
#pragma unroll
    for (int fm = 0; fm < 2; fm++)
#pragma unroll
        for (int fn = 0; fn < 4; fn++)
            wmma::store_matrix_sync(Cs + (wy * 32 + fm * 16) * 192 + wx * 64 + fn * 16,
                                    acc[fm][fn], 192, wmma::mem_row_major);
    __syncthreads();
}

// fp32 + bias epilogue for 128x192 tile
__device__ __forceinline__ void f_store192(char* smem, int tid, const float* biasv, int n0,
                                           float* Cp, long long crow0, int ldc)
{
    float* Cs = reinterpret_cast<float*>(smem);
#pragma unroll
    for (int it = 0; it < 16; it++) {
        int flat = it * 384 + tid;           // 6144 float4 units
        int row = flat / 48, q = flat - row * 48;
        float4 v = *reinterpret_cast<const float4*>(Cs + row * 192 + q * 4);
        if (biasv) {
            const float4 bv = *reinterpret_cast<const float4*>(biasv + n0 + q * 4);
            v.x += bv.x; v.y += bv.y; v.z += bv.z; v.w += bv.w;
        }
        *reinterpret_cast<float4*>(Cp + (size_t)(crow0 + row) * ldc + n0 + q * 4) = v;
    }
}

__global__ __launch_bounds__(384, 1)
void fused_scan_mem(const float* __restrict__ Q, const float* __restrict__ rw,
                    const float* __restrict__ state0, const float* __restrict__ W_hh,
                    const float* __restrict__ b_ih, const float* __restrict__ b_hh,
                    float* __restrict__ state_out,
                    __nv_bfloat16* __restrict__ sth, __nv_bfloat16* __restrict__ stl,
                    const __nv_bfloat16* __restrict__ Wmh, const __nv_bfloat16* __restrict__ Wml,
                    const float* __restrict__ bm, float* __restrict__ Cmem,
                    const __nv_bfloat16* __restrict__ Mch, const __nv_bfloat16* __restrict__ Mcl,
                    const float* __restrict__ pbias, float* __restrict__ Cpool,
                    const __nv_bfloat16* __restrict__ W1h, const __nv_bfloat16* __restrict__ W1l,
                    const float* __restrict__ b1cat, const float* __restrict__ W2cat,
                    const float* __restrict__ bh2, const float* __restrict__ bt2, const float* __restrict__ bv2,
                    float* __restrict__ oH, float* __restrict__ oT, float* __restrict__ oV,
                    const __nv_bfloat16* __restrict__ prjh, const __nv_bfloat16* __restrict__ prjl,
                    const __nv_bfloat16* __restrict__ Wihh, const __nv_bfloat16* __restrict__ Wihl,
                    float* __restrict__ Qout)
{
    extern __shared__ __align__(16) char smem[];
    const int tid = threadIdx.x;

    if (blockIdx.x < 64) {
        // ================= SCAN ROLE =================
        float* hbuf = reinterpret_cast<float*>(smem);
        float* gh   = hbuf + 128;
        const int b = blockIdx.x >> 3;
        const int e = blockIdx.x & 7;
        const int j = tid;

        unsigned long long w2r[64];
        {
            const unsigned long long* wr = reinterpret_cast<const unsigned long long*>(W_hh + (size_t)j * DSq);
#pragma unroll
            for (int i = 0; i < 64; i++) w2r[i] = wr[i];
        }
        if (j < 32) reinterpret_cast<float4*>(hbuf)[j] = reinterpret_cast<const float4*>(state0 + e * DSq)[j];
        const float bhh = b_hh[j];
        float bir = 0.f, biz = 0.f, bin = 0.f;
        if (j < DSq) { bir = b_ih[j]; biz = b_ih[DSq + j]; bin = b_ih[2 * DSq + j]; }
        __syncthreads();

        const ulonglong2* hs2 = reinterpret_cast<const ulonglong2*>(hbuf);

        if (j == 0) { while (atomicAdd(&g_prog[128 + b * 8], 0) < 2) { } }
        __syncthreads();
        __threadfence();

        float qr = 0.f, qz = 0.f, qn = 0.f, rwv = 0.f;
        if (j < DSq) {
            const float* qp = Q + (size_t)(b * Tq) * (3 * DSq);
            qr = qp[j]; qz = qp[DSq + j]; qn = qp[2 * DSq + j];
            rwv = rw[(size_t)(b * Tq) * NEq + e];
        }

        for (int t = 0; t < Tq; t++) {
            const int row = b * Tq + t;
            const int tn = t + 1;
            if (tn < Tq && (tn & 127) == 0) {
                if (j == 0) { while (atomicAdd(&g_prog[128 + b * 8 + (tn >> 7)], 0) < 2) { } }
                __syncthreads();
                __threadfence();
            }
            float nqr = 0.f, nqz = 0.f, nqn = 0.f, nrw = 0.f;
            if (tn < Tq && j < DSq) {
                const float* qp = Q + (size_t)(row + 1) * (3 * DSq);
                nqr = __ldg(qp + j); nqz = __ldg(qp + DSq + j); nqn = __ldg(qp + 2 * DSq + j);
                nrw = __ldg(rw + (size_t)(row + 1) * NEq + e);
            }
            unsigned long long a0 = 0, a1 = 0, a2 = 0, a3 = 0;
#pragma unroll
            for (int i = 0; i < 32; i += 2) {
                ulonglong2 h0 = hs2[i];
                ulonglong2 h1 = hs2[i + 1];
                a0 = fma_f32x2(w2r[i * 2 + 0], h0.x, a0);
                a1 = fma_f32x2(w2r[i * 2 + 1], h0.y, a1);
                a2 = fma_f32x2(w2r[i * 2 + 2], h1.x, a2);
                a3 = fma_f32x2(w2r[i * 2 + 3], h1.y, a3);
            }
            float acc = ((lo_f(a0) + hi_f(a0)) + (lo_f(a1) + hi_f(a1)))
                      + ((lo_f(a2) + hi_f(a2)) + (lo_f(a3) + hi_f(a3)));
            gh[j] = acc + bhh;
            __syncthreads();
            if (j < DSq) {
                float gir = fmaf(rwv, qr, bir);
                float giz = fmaf(rwv, qz, biz);
                float gin = fmaf(rwv, qn, bin);
                float r = __fdividef(1.f, 1.f + __expf(-(gir + gh[j])));
                float z = __fdividef(1.f, 1.f + __expf(-(giz + gh[DSq + j])));
                float xn = fmaf(r, gh[2 * DSq + j], gin);
                float ex = __expf(-2.f * xn);
                float n = __fdividef(1.f - ex, 1.f + ex);
                float hnew = fmaf(z, hbuf[j] - n, n);
                hbuf[j] = hnew;
                size_t idx = (((size_t)row) * NEq + e) * DSq + j;
                state_out[idx] = hnew;
                __nv_bfloat16 hh = __float2bfloat16(hnew);
                sth[idx] = hh;
                stl[idx] = __float2bfloat16(hnew - __bfloat162float(hh));
            }
            __syncthreads();
            if ((t & 63) == 63 && j == 0) {
                __threadfence();
                atomicAdd(&g_prog[b * 16 + (t >> 6)], 1);
            }
            qr = nqr; qz = nqz; qn = nqn; rwv = nrw;
        }
    } else if (blockIdx.x < 192) {
        // ================= Q PRODUCER ROLE (128x192, K=128) =================
        const uint32_t sb = smem_u32(smem);
        const int g2 = blockIdx.x - 64;       // 0..127, chunk-major
        const int tc = g2 >> 4;               // 0..7
        const int b = (g2 >> 1) & 7;
        const int half = g2 & 1;
        const long long row0 = (long long)b * 1024 + (long long)tc * 128;
        const int n0 = half * 192;

        f_loop192(smem, sb, tid, prjh, prjl, row0, DSq, Wihh, Wihl, n0, DSq, 2);
        f_store192(smem, tid, nullptr, n0, Qout, row0, 3 * DSq);
        __syncthreads();
        if (tid == 0) {
            __threadfence();
            atomicAdd(&g_prog[128 + b * 8 + tc], 1);
        }
    } else {
        // ================= CONSUMER ROLES =================
        const uint32_t sb = smem_u32(smem);
        const int g = blockIdx.x - 192;
        const int pair = g / 11;
        const int rem = g - pair * 11;
        int r, s;
        if (rem < 5) { r = 2 * pair;     s = rem; }
        else         { r = 2 * pair + 1; s = rem - 5; }

        if (s < 4) {
            // ---- memory tile 128x192, K=128 ----
            const int b = r & 7, tb16 = r >> 3;
            const long long row0 = (long long)b * 8192 + (long long)tb16 * 128;
            const int n0 = s * 192;
            const int kflag = b * 16 + (tb16 >> 2);
            if (tid == 0) { while (atomicAdd(&g_prog[kflag], 0) < 8) { } }
            __syncthreads();
            __threadfence();
            f_loop192(smem, sb, tid, sth, stl, row0, DSq, Wmh, Wml, n0, DSq, 2);
            f_store192(smem, tid, bm, n0, Cmem, row0, Dq);
        } else if (s == 4) {
            // ---- heads tile 128x192, K=128, GELU.W2 epilogue ----
            const int b = r & 7, tb16 = r >> 3;
            const long long row0 = (long long)b * 8192 + (long long)tb16 * 128;
            const int kflag = b * 16 + (tb16 >> 2);
            if (tid == 0) { while (atomicAdd(&g_prog[kflag], 0) < 8) { } }
            __syncthreads();
            __threadfence();
            f_loop192(smem, sb, tid, sth, stl, row0, DSq, W1h, W1l, 0, DSq, 2);
            {
                float* Cs = reinterpret_cast<float*>(smem);
                const int row = tid & 127;
                const int head = tid >> 7;
                const float* cr = Cs + row * 192 + head * 64;
                float dot = 0.f;
#pragma unroll
                for (int q = 0; q < 16; q++) {
                    int qq = (q + row) & 15;
                    float4 v = *reinterpret_cast<const float4*>(cr + qq * 4);
                    int col = head * 64 + qq * 4;
                    dot = fmaf(gelu_exact(v.x + __ldg(b1cat + col + 0)), __ldg(W2cat + col + 0), dot);
                    dot = fmaf(gelu_exact(v.y + __ldg(b1cat + col + 1)), __ldg(W2cat + col + 1), dot);
                    dot = fmaf(gelu_exact(v.z + __ldg(b1cat + col + 2)), __ldg(W2cat + col + 2), dot);
                    dot = fmaf(gelu_exact(v.w + __ldg(b1cat + col + 3)), __ldg(W2cat + col + 3), dot);
                }
                float* op = (head == 0) ? oH : (head == 1) ? oT : oV;
                float b2 = (head == 0) ? __ldg(bh2) : (head == 1) ? __ldg(bt2) : __ldg(bv2);
                op[row0 + row] = dot + b2;
            }
        } else {
            // ---- pooled tile 128x192, K=1024 ----
            const int p = pair;                 // 0..255
            const int rt = p >> 2;              // 0..63
            const int b = rt & 7, tbp = rt >> 3;
            const long long row0 = (long long)b * 1024 + (long long)tbp * 128;
            const int n0 = (p & 3) * 192;
            const int kflag = b * 16 + 2 * tbp + 1;
            if (tid == 0) { while (atomicAdd(&g_prog[kflag], 0) < 8) { } }
            __syncthreads();
            __threadfence();
            f_loop192(smem, sb, tid, sth, stl, row0, NEq * DSq, Mch, Mcl, n0, NEq * DSq, 16);
            f_store192(smem, tid, pbias, n0, Cpool, row0, Dq);
        }
    }
}

// ---------------------------------------------------------------------------
// MERGED prep + route(+cvt) + pbias
// ---------------------------------------------------------------------------
#define PREP_TOTAL (DSq*Dq + 3*DSq*DSq + Dq*DSq + Dq*DSq + 256*DSq + 256 + (long long)Dq*NEq*Dq)
#define PREP_B     ((int)((PREP_TOTAL + 255) / 256))

__global__ __launch_bounds__(256)
void prep_all(const float* __restrict__ Wi, const float* __restrict__ W_ih,
              const float* __restrict__ Wm, const float* __restrict__ Ws,
              const float* __restrict__ Wh1, const float* __restrict__ Wt1,
              const float* __restrict__ Wv1,
              const float* __restrict__ bh1, const float* __restrict__ bt1,
              const float* __restrict__ bv1,
              const float* __restrict__ Wh2, const float* __restrict__ Wt2,
              const float* __restrict__ Wv2,
              const float* __restrict__ h_seq, const float* __restrict__ ek,
              float* __restrict__ rwout,
              __nv_bfloat16* __restrict__ hsh, __nv_bfloat16* __restrict__ hsl,
              const float* __restrict__ bm, const float* __restrict__ bs,
              float* __restrict__ pb)
{
    const int bid = blockIdx.x;
    if (bid < PREP_B) {
        if (bid == 0 && threadIdx.x < 192) g_prog[threadIdx.x] = 0;
        const int N_Wi = DSq * Dq, N_Wih = 3 * DSq * DSq, N_Wm = Dq * DSq;
        const int N_W1 = 256 * DSq;
        const long long N_Ws = (long long)Dq * NEq * Dq;
        long long idx = (long long)bid * 256 + threadIdx.x;
        __nv_bfloat16 h, l;
        if (idx < N_Wi)  { hilo(Wi[idx], h, l);   g_Wi_hi[idx] = h;  g_Wi_lo[idx] = l;  return; }
        idx -= N_Wi;
        if (idx < N_Wih) { hilo(W_ih[idx], h, l); g_Wih_hi[idx] = h; g_Wih_lo[idx] = l; return; }
        idx -= N_Wih;
        if (idx < N_Wm)  { hilo(Wm[idx], h, l);   g_Wm_hi[idx] = h;  g_Wm_lo[idx] = l;  return; }
        idx -= N_Wm;
        if (idx < N_Wm) {
            int j = (int)(idx / DSq), k = (int)(idx % DSq);
            hilo(Wm[idx], h, l);
            g_WmT_hi[(size_t)k * Dq + j] = h; g_WmT_lo[(size_t)k * Dq + j] = l; return;
        }
        idx -= N_Wm;
        if (idx < N_W1) {
            int r = (int)(idx / DSq), c = (int)(idx % DSq);
            float v = (r < 64) ? Wh1[r * DSq + c] : (r < 128) ? Wt1[(r - 64) * DSq + c]
                    : (r < 192) ? Wv1[(r - 128) * DSq + c] : 0.f;
            hilo(v, h, l); g_W1_hi[idx] = h; g_W1_lo[idx] = l; return;
        }
        idx -= N_W1;
        if (idx < 256) {
            int i = (int)idx;
            g_b1cat[i] = (i < 64) ? bh1[i] : (i < 128) ? bt1[i - 64] : (i < 192) ? bv1[i - 128] : 0.f;
            g_W2cat[i] = (i < 64) ? Wh2[i] : (i < 128) ? Wt2[i - 64] : (i < 192) ? Wv2[i - 128] : 0.f;
            return;
        }
        idx -= 256;
        if (idx < N_Ws) { hilo(Ws[idx], h, l); g_Ws_hi[idx] = h; g_Ws_lo[idx] = l; }
        return;
    }
    if (bid < PREP_B + ROWS) {
        const int row = bid - PREP_B;
        const int w = threadIdx.x >> 5, lane = threadIdx.x & 31;
        const float* hr = h_seq + (size_t)row * Dq;
        const float* er = ek + (size_t)w * Dq;
        float s = 0.f;
#pragma unroll 4
        for (int k = lane; k < Dq; k += 32) s = fmaf(hr[k], er[k], s);
#pragma unroll
        for (int o = 16; o; o >>= 1) s += __shfl_xor_sync(0xffffffffu, s, o);
        __shared__ float lg[NEq];
        if (lane == 0) lg[w] = s;
#pragma unroll
        for (int i = threadIdx.x; i < Dq; i += 256) {
            __nv_bfloat16 h, l; hilo(hr[i], h, l);
            hsh[(size_t)row * Dq + i] = h;
            hsl[(size_t)row * Dq + i] = l;
        }
        __syncthreads();
        if (threadIdx.x == 0) {
            const float inv = 0.036084391824351615f;
            float v[NEq], m = -1e30f;
#pragma unroll
            for (int e = 0; e < NEq; e++) { v[e] = lg[e] * inv; m = fmaxf(m, v[e]); }
            float den = 0.f;
#pragma unroll
            for (int e = 0; e < NEq; e++) { v[e] = __expf(v[e] - m); den += v[e]; }
            float id = 1.f / den;
#pragma unroll
            for (int e = 0; e < NEq; e++) rwout[(size_t)row * NEq + e] = v[e] * id;
        }
        return;
    }
    {
        const int d = bid - PREP_B - ROWS;
        const int tid = threadIdx.x;
        float s = 0.f;
        int jm = tid;                         // running j % Dq (no modulo)
        for (int j = tid; j < NEq * Dq; j += 256) {
            s = fmaf(bm[jm], Ws[(size_t)d * (NEq * Dq) + j], s);
            jm += 256; if (jm >= Dq) jm -= Dq;
        }
        __shared__ float red[256];
        red[tid] = s; __syncthreads();
        for (int o = 128; o; o >>= 1) { if (tid < o) red[tid] += red[tid + o]; __syncthreads(); }
        if (tid == 0) pb[d] = red[0] + bs[d];
    }
}

// ---------------------------------------------------------------------------
// Launch
// ---------------------------------------------------------------------------
extern "C" void kernel_launch(void* const* d_in, const int* in_sizes, int n_in,
                              void* d_out, int out_size)
{
    const float* h_seq = (const float*)d_in[0];
    const float* ek    = (const float*)d_in[1];
    const float* state0= (const float*)d_in[2];
    const float* Wi    = (const float*)d_in[3];
    const float* bi    = (const float*)d_in[4];
    const float* W_ih  = (const float*)d_in[5];
    const float* W_hh  = (const float*)d_in[6];
    const float* b_ih  = (const float*)d_in[7];
    const float* b_hh  = (const float*)d_in[8];
    const float* Wm    = (const float*)d_in[9];
    const float* bm    = (const float*)d_in[10];
    const float* Ws    = (const float*)d_in[11];
    const float* bs    = (const float*)d_in[12];
    const float* Wh1   = (const float*)d_in[13];
    const float* bh1   = (const float*)d_in[14];
    const float* Wh2   = (const float*)d_in[15];
    const float* bh2   = (const float*)d_in[16];
    const float* Wt1   = (const float*)d_in[17];
    const float* bt1   = (const float*)d_in[18];
    const float* Wt2   = (const float*)d_in[19];
    const float* bt2   = (const float*)d_in[20];
    const float* Wv1   = (const float*)d_in[21];
    const float* bv1   = (const float*)d_in[22];
    const float* Wv2   = (const float*)d_in[23];
    const float* bv2   = (const float*)d_in[24];
    float* out = (float*)d_out;

    cudaFuncSetAttribute(gemm_proj_mc, cudaFuncAttributeMaxDynamicSharedMemorySize, SM_BYTES);
    cudaFuncSetAttribute(fused_scan_mem, cudaFuncAttributeMaxDynamicSharedMemorySize, F_SM);

#define SYMF(p, s) float* p; cudaGetSymbolAddress((void**)&p, s)
#define SYMB(p, s) __nv_bfloat16* p; cudaGetSymbolAddress((void**)&p, s)
    SYMB(p_hsh, g_hseq_hi);  SYMB(p_hsl, g_hseq_lo);
    SYMB(p_sth, g_state_hi); SYMB(p_stl, g_state_lo);
    SYMB(p_prh, g_projh);    SYMB(p_prl, g_projl);
    SYMB(p_wsh, g_Ws_hi);    SYMB(p_wsl, g_Ws_lo);
    SYMB(p_wih, g_Wi_hi);    SYMB(p_wil, g_Wi_lo);
    SYMB(p_whh, g_Wih_hi);   SYMB(p_whl, g_Wih_lo);
    SYMB(p_wmh, g_Wm_hi);    SYMB(p_wml, g_Wm_lo);
    SYMB(p_wth, g_WmT_hi);   SYMB(p_wtl, g_WmT_lo);
    SYMB(p_mch, g_Mc_hi);    SYMB(p_mcl, g_Mc_lo);
    SYMB(p_w1h, g_W1_hi);    SYMB(p_w1l, g_W1_lo);
    SYMF(p_Q, g_Q); SYMF(p_pb, g_pbias);
    SYMF(p_b1, g_b1cat);  SYMF(p_w2, g_W2cat);

    // 1) MERGED prep + route + pbias (+flag reset)
    prep_all<<<PREP_B + ROWS + Dq, 256>>>(Wi, W_ih, Wm, Ws, Wh1, Wt1, Wv1,
                                          bh1, bt1, bv1, Wh2, Wt2, Wv2,
                                          h_seq, ek, out + RW_OFF, p_hsh, p_hsl,
                                          bm, bs, p_pb);

    // 2) MERGED proj + Mc (112 blocks)
    gemm_proj_mc<<<112, 512, SM_BYTES>>>(p_hsh, p_hsl, p_wih, p_wil, bi,
                                         p_prh, p_prl,
                                         p_wsh, p_wsl, p_wth, p_wtl,
                                         p_mch, p_mcl);

    // 3) FUSED: scan (64) + Q producers (128) + consumers (2816)
    fused_scan_mem<<<64 + 128 + 2816, 384, F_SM>>>(p_Q, out + RW_OFF, state0, W_hh, b_ih, b_hh,
                                                   out + STATE_OFF, p_sth, p_stl,
                                                   p_wmh, p_wml, bm, out + MEM_OFF,
                                                   p_mch, p_mcl, p_pb, out + POOLED_OFF,
                                                   p_w1h, p_w1l, p_b1, p_w2, bh2, bt2, bv2,
                                                   out + HOLDER_OFF, out + TAGGED_OFF, out + VISIBLE_OFF,
                                                   p_prh, p_prl, p_whh, p_whl, p_Q);

    (void)in_sizes; (void)n_in; (void)out_size;
}

// round 17
// speedup vs baseline: 1.0215x; 1.0215x over previous
#include <cuda_runtime.h>
#include <cuda_bf16.h>
#include <mma.h>
#include <math.h>
#include <stdint.h>

using namespace nvcuda;

#define Bq   8
#define Tq   1024
#define Dq   768
#define NEq  8
#define DSq  128
#define ROWS (Bq*Tq)            // 8192
#define SROWS (Bq*Tq*NEq)       // 65536

#define POOLED_OFF  0ll
#define MEM_OFF     6291456ll
#define STATE_OFF   56623104ll
#define HOLDER_OFF  65011712ll
#define TAGGED_OFF  65077248ll
#define VISIBLE_OFF 65142784ll
#define RW_OFF      65208320ll

// ---------------------------------------------------------------------------
// Scratch
// ---------------------------------------------------------------------------
__device__ __align__(16) __nv_bfloat16 g_hseq_hi[ROWS*Dq],    g_hseq_lo[ROWS*Dq];
__device__ __align__(16) __nv_bfloat16 g_state_hi[SROWS*DSq], g_state_lo[SROWS*DSq];
__device__ __align__(16) __nv_bfloat16 g_projh[ROWS*DSq],     g_projl[ROWS*DSq];
__device__ __align__(16) __nv_bfloat16 g_Ws_hi[Dq*NEq*Dq],    g_Ws_lo[Dq*NEq*Dq];
__device__ __align__(16) __nv_bfloat16 g_Wi_hi[DSq*Dq],       g_Wi_lo[DSq*Dq];
__device__ __align__(16) __nv_bfloat16 g_Wih_hi[3*DSq*DSq],   g_Wih_lo[3*DSq*DSq];
__device__ __align__(16) __nv_bfloat16 g_Wm_hi[Dq*DSq],       g_Wm_lo[Dq*DSq];
__device__ __align__(16) __nv_bfloat16 g_WmT_hi[DSq*Dq],      g_WmT_lo[DSq*Dq];
__device__ __align__(16) __nv_bfloat16 g_Mc_hi[Dq*NEq*DSq],   g_Mc_lo[Dq*NEq*DSq];
__device__ __align__(16) __nv_bfloat16 g_W1_hi[256*DSq],      g_W1_lo[256*DSq];
__device__ __align__(16) float g_Q[ROWS*3*DSq];
__device__ __align__(16) float g_pbias[Dq];
__device__ __align__(16) float g_b1cat[256];
__device__ __align__(16) float g_W2cat[256];
__device__ int g_prog[128];        // per (b, 64-step chunk) completion counters

// ---------------------------------------------------------------------------
// helpers
// ---------------------------------------------------------------------------
__device__ __forceinline__ unsigned long long fma_f32x2(unsigned long long a, unsigned long long b, unsigned long long c) {
    unsigned long long d;
    asm("fma.rn.f32x2 %0, %1, %2, %3;" : "=l"(d) : "l"(a), "l"(b), "l"(c));
    return d;
}
__device__ __forceinline__ float lo_f(unsigned long long v) { return __uint_as_float((uint32_t)v); }
__device__ __forceinline__ float hi_f(unsigned long long v) { return __uint_as_float((uint32_t)(v >> 32)); }

__device__ __forceinline__ uint32_t smem_u32(const void* p) {
    uint32_t a;
    asm("{ .reg .u64 t; cvta.to.shared.u64 t, %1; cvt.u32.u64 %0, t; }" : "=r"(a) : "l"(p));
    return a;
}
#define CP_COMMIT() asm volatile("cp.async.commit_group;" ::: "memory")
#define CP_WAIT0()  asm volatile("cp.async.wait_group 0;" ::: "memory")
#define CP_WAIT1()  asm volatile("cp.async.wait_group 1;" ::: "memory")

__device__ __forceinline__ void cp16(uint32_t d, const void* s) {
    asm volatile("cp.async.cg.shared.global [%0], [%1], 16;" :: "r"(d), "l"(s));
}

__device__ __forceinline__ void hilo(float v, __nv_bfloat16& h, __nv_bfloat16& l) {
    h = __float2bfloat16(v);
    l = __float2bfloat16(v - __bfloat162float(h));
}

__device__ __forceinline__ float gelu_exact(float x) {
    return 0.5f * x * (1.0f + erff(x * 0.70710678118654752f));
}

// ---------------------------------------------------------------------------
// GEMM tiling constants: block 128x128, BK=64, 512 thr, 16 warps.
// ---------------------------------------------------------------------------
#define BKT    64
#define LDSK   72
#define E_ALO  9216
#define E_BHI  18432
#define E_BLO  27648
#define E_BUF  36864
#define TILE_B 18432
#define BUF_B  73728
#define SM_BYTES 147456

__device__ __forceinline__ void stage_async(uint32_t sdst, const __nv_bfloat16* __restrict__ g,
                                            long long row0, int k0, int ld, int tid)
{
#pragma unroll
    for (int it = 0; it < 2; it++) {
        int flat = it * 512 + tid;
        int row = flat >> 3, q = flat & 7;
        cp16(sdst + row * (LDSK * 2) + q * 16, g + (row0 + row) * (long long)ld + k0 + q * 8);
    }
}

__device__ __forceinline__ void stage4(uint32_t bufb,
                                       const __nv_bfloat16* Ahi, const __nv_bfloat16* Alo,
                                       const __nv_bfloat16* Bhi, const __nv_bfloat16* Blo,
                                       long long m0, int n0, int ka, int kb, int lda, int ldb, int tid)
{
    stage_async(bufb,              Ahi, m0, ka, lda, tid);
    stage_async(bufb + TILE_B,     Alo, m0, ka, lda, tid);
    stage_async(bufb + 2 * TILE_B, Bhi, n0, kb, ldb, tid);
    stage_async(bufb + 3 * TILE_B, Blo, n0, kb, ldb, tid);
    CP_COMMIT();
}

// 16-warp, 128x128 body (proj / Mc / Q)
__device__ __forceinline__ void gemm128_body(
    char* smem, uint32_t sb, int tid,
    const __nv_bfloat16* __restrict__ Ahi, const __nv_bfloat16* __restrict__ Alo, int lda, int aK0,
    const __nv_bfloat16* __restrict__ Bhi, const __nv_bfloat16* __restrict__ Blo, int ldb,
    long long m0, int n0, int cOff,
    float* __restrict__ C, int ldc,
    const float* __restrict__ bias, int nChunks,
    __nv_bfloat16* __restrict__ outH, __nv_bfloat16* __restrict__ outL)
{
    __nv_bfloat16* s16 = reinterpret_cast<__nv_bfloat16*>(smem);
    const int wid = tid >> 5;
    const int wy = wid >> 2, wx = wid & 3;

    wmma::fragment<wmma::accumulator, 16, 16, 16, float> acc[2][2];
#pragma unroll
    for (int i = 0; i < 2; i++)
#pragma unroll
        for (int j = 0; j < 2; j++) wmma::fill_fragment(acc[i][j], 0.0f);

    stage4(sb, Ahi, Alo, Bhi, Blo, m0, n0, aK0, 0, lda, ldb, tid);

    for (int c = 0; c < nChunks; c++) {
        if (c + 1 < nChunks) {
            stage4(sb + ((c + 1) & 1) * BUF_B, Ahi, Alo, Bhi, Blo, m0, n0,
                   aK0 + (c + 1) * BKT, (c + 1) * BKT, lda, ldb, tid);
            CP_WAIT1();
        } else {
            CP_WAIT0();
        }
        __syncthreads();
        const __nv_bfloat16* base = s16 + (c & 1) * E_BUF;
#pragma unroll
        for (int ks = 0; ks < BKT; ks += 16) {
            wmma::fragment<wmma::matrix_b, 16, 16, 16, __nv_bfloat16, wmma::col_major> bh[2], bl[2];
            wmma::fragment<wmma::matrix_a, 16, 16, 16, __nv_bfloat16, wmma::row_major> ah[2], al[2];
#pragma unroll
            for (int fn = 0; fn < 2; fn++) {
                const int nb = wx * 32 + fn * 16;
                wmma::load_matrix_sync(bh[fn], base + E_BHI + nb * LDSK + ks, LDSK);
                wmma::load_matrix_sync(bl[fn], base + E_BLO + nb * LDSK + ks, LDSK);
            }
#pragma unroll
            for (int fm = 0; fm < 2; fm++) {
                const int mb = wy * 32 + fm * 16;
                wmma::load_matrix_sync(ah[fm], base + mb * LDSK + ks, LDSK);
                wmma::load_matrix_sync(al[fm], base + E_ALO + mb * LDSK + ks, LDSK);
            }
#pragma unroll
            for (int fm = 0; fm < 2; fm++)
#pragma unroll
                for (int fn = 0; fn < 2; fn++)
                    wmma::mma_sync(acc[fm][fn], ah[fm], bh[fn], acc[fm][fn]);
#pragma unroll
            for (int fm = 0; fm < 2; fm++)
#pragma unroll
                for (int fn = 0; fn < 2; fn++)
                    wmma::mma_sync(acc[fm][fn], ah[fm], bl[fn], acc[fm][fn]);
#pragma unroll
            for (int fm = 0; fm < 2; fm++)
#pragma unroll
                for (int fn = 0; fn < 2; fn++)
                    wmma::mma_sync(acc[fm][fn], al[fm], bh[fn], acc[fm][fn]);
        }
        __syncthreads();
    }

    float* Cs = reinterpret_cast<float*>(smem);
#pragma unroll
    for (int fm = 0; fm < 2; fm++)
#pragma unroll
        for (int fn = 0; fn < 2; fn++)
            wmma::store_matrix_sync(Cs + (wy * 32 + fm * 16) * 128 + wx * 32 + fn * 16,
                                    acc[fm][fn], 128, wmma::mem_row_major);
    __syncthreads();
#pragma unroll
    for (int it = 0; it < 8; it++) {
        int flat = it * 512 + tid;
        int row = flat >> 5, q = flat & 31;
        float4 v = *reinterpret_cast<const float4*>(Cs + row * 128 + q * 4);
        if (bias) {
            const float4 bv = *reinterpret_cast<const float4*>(bias + n0 + q * 4);
            v.x += bv.x; v.y += bv.y; v.z += bv.z; v.w += bv.w;
        }
        size_t co = (size_t)(m0 + row) * ldc + cOff + q * 4;
        if (C) *reinterpret_cast<float4*>(C + co) = v;
        if (outH) {
            __nv_bfloat16 h0,l0,h1,l1,h2,l2,h3,l3;
            hilo(v.x,h0,l0); hilo(v.y,h1,l1); hilo(v.z,h2,l2); hilo(v.w,h3,l3);
            __nv_bfloat162 ph0 = {h0,h1}, ph1 = {h2,h3}, pl0 = {l0,l1}, pl1 = {l2,l3};
            *reinterpret_cast<__nv_bfloat162*>(outH + co)     = ph0;
            *reinterpret_cast<__nv_bfloat162*>(outH + co + 2) = ph1;
            *reinterpret_cast<__nv_bfloat162*>(outL + co)     = pl0;
            *reinterpret_cast<__nv_bfloat162*>(outL + co + 2) = pl1;
        }
    }
}

// ---------------------------------------------------------------------------
// Q GEMM (standalone): Q = proj @ W_ih^T   grid (3, 64)
// ---------------------------------------------------------------------------
__global__ __launch_bounds__(512, 1)
void gemm_tc(const __nv_bfloat16* __restrict__ Ahi, const __nv_bfloat16* __restrict__ Alo, int lda,
             const __nv_bfloat16* __restrict__ Bhi, const __nv_bfloat16* __restrict__ Blo, int ldb,
             float* __restrict__ C, int ldc, int nChunks)
{
    extern __shared__ __align__(16) char smem[];
    gemm128_body(smem, smem_u32(smem), threadIdx.x,
                 Ahi, Alo, lda, 0, Bhi, Blo, ldb,
                 (long long)blockIdx.y * 128, blockIdx.x * 128, blockIdx.x * 128,
                 C, ldc, nullptr, nChunks, nullptr, nullptr);
}

// ---------------------------------------------------------------------------
// proj + Mc combined GEMM (112 blocks)
// ---------------------------------------------------------------------------
__global__ __launch_bounds__(512, 1)
void gemm_proj_mc(const __nv_bfloat16* __restrict__ hseqh, const __nv_bfloat16* __restrict__ hseql,
                  const __nv_bfloat16* __restrict__ Wih, const __nv_bfloat16* __restrict__ Wil,
                  const float* __restrict__ bi,
                  __nv_bfloat16* __restrict__ projh, __nv_bfloat16* __restrict__ projl,
                  const __nv_bfloat16* __restrict__ Wsh, const __nv_bfloat16* __restrict__ Wsl,
                  const __nv_bfloat16* __restrict__ WmTh, const __nv_bfloat16* __restrict__ WmTl,
                  __nv_bfloat16* __restrict__ Mch, __nv_bfloat16* __restrict__ Mcl)
{
    extern __shared__ __align__(16) char smem[];
    const int bid = blockIdx.x;
    if (bid < 64) {
        gemm128_body(smem, smem_u32(smem), threadIdx.x,
                     hseqh, hseql, Dq, 0, Wih, Wil, Dq,
                     (long long)bid * 128, 0, 0,
                     nullptr, DSq, bi, Dq / BKT, projh, projl);
    } else {
        const int idx = bid - 64;
        const int m = idx >> 3, e = idx & 7;
        gemm128_body(smem, smem_u32(smem), threadIdx.x,
                     Wsh, Wsl, NEq * Dq, e * Dq, WmTh, WmTl, Dq,
                     (long long)m * 128, 0, e * DSq,
                     nullptr, NEq * DSq, nullptr, Dq / BKT, Mch, Mcl);
    }
}

// ---------------------------------------------------------------------------
// FUSED scan + {memory, pooled, heads} persistent kernel (384 threads).
// Blocks 0..63: scan; publish g_prog[b*16+k] per 64-step chunk.
// Consumers: g = bid-64, r = g/10, s = g%10.
//   s<8 : memory tile 128x96 (s==0 also reconstructs fp32 state_out)
//   s==8: pooled tile 128x96 (K=1024)
//   s==9: heads tile 128x192 + GELU.W2 epilogue
// ---------------------------------------------------------------------------
#define F_EALO  9216
#define F_EBHI  18432
#define F_EBLO  25344
#define F_EBUF  32256
#define F_TA_B  18432
#define F_BUF_B 64512
#define H_EBHI  18432
#define H_EBLO  32256
#define H_EBUF  46080
#define H_BUF_B 92160
#define F_SM    184320

__device__ __forceinline__ void f_stageA(uint32_t sdst, const __nv_bfloat16* __restrict__ g,
                                         long long row0, int k0, int ld, int tid)
{
#pragma unroll
    for (int it = 0; it < 3; it++) {
        int u = it * 384 + tid;
        if (u < 1024) {
            int row = u >> 3, q = u & 7;
            cp16(sdst + row * (LDSK * 2) + q * 16, g + (row0 + row) * (long long)ld + k0 + q * 8);
        }
    }
}
__device__ __forceinline__ void f_stageB(uint32_t sdst, const __nv_bfloat16* __restrict__ g,
                                         int n0, int k0, int ld, int tid)
{
#pragma unroll
    for (int it = 0; it < 2; it++) {
        int u = it * 384 + tid;
        int row = u >> 3, q = u & 7;
        cp16(sdst + row * (LDSK * 2) + q * 16, g + (size_t)(n0 + row) * ld + k0 + q * 8);
    }
}
__device__ __forceinline__ void f_stageB192(uint32_t sdst, const __nv_bfloat16* __restrict__ g,
                                            int k0, int tid)
{
#pragma unroll
    for (int it = 0; it < 4; it++) {
        int u = it * 384 + tid;
        int row = u >> 3, q = u & 7;
        cp16(sdst + row * (LDSK * 2) + q * 16, g + (size_t)row * DSq + k0 + q * 8);
    }
}

__device__ __forceinline__ void f_stage_all(uint32_t bufb,
                                            const __nv_bfloat16* Ahi, const __nv_bfloat16* Alo, long long row0, int lda,
                                            const __nv_bfloat16* Bhi, const __nv_bfloat16* Blo, int n0, int ldb,
                                            int k0, int tid)
{
    f_stageA(bufb,              Ahi, row0, k0, lda, tid);
    f_stageA(bufb + F_TA_B,     Alo, row0, k0, lda, tid);
    f_stageB(bufb + F_EBHI * 2, Bhi, n0, k0, ldb, tid);
    f_stageB(bufb + F_EBLO * 2, Blo, n0, k0, ldb, tid);
    CP_COMMIT();
}

// 12-warp 128x96 gemm + fp32 epilogue
__device__ __forceinline__ void f_gemm96(char* smem, uint32_t sb, int tid,
                                         const __nv_bfloat16* Ahi, const __nv_bfloat16* Alo, long long row0, int lda,
                                         const __nv_bfloat16* Bhi, const __nv_bfloat16* Blo, int n0, int ldb,
                                         int nCh, const float* biasv, float* Cp, long long crow0, int ldc)
{
    __nv_bfloat16* s16 = reinterpret_cast<__nv_bfloat16*>(smem);
    const int wid = tid >> 5;
    const int wy = wid & 3;
    const int wx = wid >> 2;

    wmma::fragment<wmma::accumulator, 16, 16, 16, float> acc[2][2];
#pragma unroll
    for (int i = 0; i < 2; i++)
#pragma unroll
        for (int jj = 0; jj < 2; jj++) wmma::fill_fragment(acc[i][jj], 0.0f);

    f_stage_all(sb, Ahi, Alo, row0, lda, Bhi, Blo, n0, ldb, 0, tid);

    for (int c = 0; c < nCh; c++) {
        if (c + 1 < nCh) {
            f_stage_all(sb + ((c + 1) & 1) * F_BUF_B, Ahi, Alo, row0, lda,
                        Bhi, Blo, n0, ldb, (c + 1) * BKT, tid);
            CP_WAIT1();
        } else {
            CP_WAIT0();
        }
        __syncthreads();
        const __nv_bfloat16* base = s16 + (c & 1) * F_EBUF;
#pragma unroll
        for (int ks = 0; ks < BKT; ks += 16) {
            wmma::fragment<wmma::matrix_b, 16, 16, 16, __nv_bfloat16, wmma::col_major> bh[2], bl[2];
            wmma::fragment<wmma::matrix_a, 16, 16, 16, __nv_bfloat16, wmma::row_major> ah[2], al[2];
#pragma unroll
            for (int fn = 0; fn < 2; fn++) {
                const int nb = wx * 32 + fn * 16;
                wmma::load_matrix_sync(bh[fn], base + F_EBHI + nb * LDSK + ks, LDSK);
                wmma::load_matrix_sync(bl[fn], base + F_EBLO + nb * LDSK + ks, LDSK);
            }
#pragma unroll
            for (int fm = 0; fm < 2; fm++) {
                const int mb = wy * 32 + fm * 16;
                wmma::load_matrix_sync(ah[fm], base + mb * LDSK + ks, LDSK);
                wmma::load_matrix_sync(al[fm], base + F_EALO + mb * LDSK + ks, LDSK);
            }
#pragma unroll
            for (int fm = 0; fm < 2; fm++)
#pragma unroll
                for (int fn = 0; fn < 2; fn++)
                    wmma::mma_sync(acc[fm][fn], ah[fm], bh[fn], acc[fm][fn]);
#pragma unroll
            for (int fm = 0; fm < 2; fm++)
#pragma unroll
                for (int fn = 0; fn < 2; fn++)
                    wmma::mma_sync(acc[fm][fn], ah[fm], bl[fn], acc[fm][fn]);
#pragma unroll
            for (int fm = 0; fm < 2; fm++)
#pragma unroll
                for (int fn = 0; fn < 2; fn++)
                    wmma::mma_sync(acc[fm][fn], al[fm], bh[fn], acc[fm][fn]);
        }
        __syncthreads();
    }

    float* Cs = reinterpret_cast<float*>(smem);
#pragma unroll
    for (int fm = 0; fm < 2; fm++)
#pragma unroll
        for (int fn = 0; fn < 2; fn++)
            wmma::store_matrix_sync(Cs + (wy * 32 + fm * 16) * 96 + wx * 32 + fn * 16,
                                    acc[fm][fn], 96, wmma::mem_row_major);
    __syncthreads();
#pragma unroll
    for (int it = 0; it < 8; it++) {
        int flat = it * 384 + tid;
        int row = flat / 24, q = flat % 24;
        float4 v = *reinterpret_cast<const float4*>(Cs + row * 96 + q * 4);
        const float4 bv = *reinterpret_cast<const float4*>(biasv + n0 + q * 4);
        v.x += bv.x; v.y += bv.y; v.z += bv.z; v.w += bv.w;
        *reinterpret_cast<float4*>(Cp + (size_t)(crow0 + row) * ldc + n0 + q * 4) = v;
    }
}

__global__ __launch_bounds__(384, 1)
void fused_scan_mem(const float* __restrict__ Q, const float* __restrict__ rw,
                    const float* __restrict__ state0, const float* __restrict__ W_hh,
                    const float* __restrict__ b_ih, const float* __restrict__ b_hh,
                    float* __restrict__ state_out,
                    __nv_bfloat16* __restrict__ sth, __nv_bfloat16* __restrict__ stl,
                    const __nv_bfloat16* __restrict__ Wmh, const __nv_bfloat16* __restrict__ Wml,
                    const float* __restrict__ bm, float* __restrict__ Cmem,
                    const __nv_bfloat16* __restrict__ Mch, const __nv_bfloat16* __restrict__ Mcl,
                    const float* __restrict__ pbias, float* __restrict__ Cpool,
                    const __nv_bfloat16* __restrict__ W1h, const __nv_bfloat16* __restrict__ W1l,
                    const float* __restrict__ b1cat, const float* __restrict__ W2cat,
                    const float* __restrict__ bh2, const float* __restrict__ bt2, const float* __restrict__ bv2,
                    float* __restrict__ oH, float* __restrict__ oT, float* __restrict__ oV)
{
    extern __shared__ __align__(16) char smem[];
    const int tid = threadIdx.x;

    if (blockIdx.x < 64) {
        // ================= SCAN ROLE =================
        float* hbuf = reinterpret_cast<float*>(smem);
        float* gh   = hbuf + 128;
        const int b = blockIdx.x >> 3;
        const int e = blockIdx.x & 7;
        const int j = tid;

        unsigned long long w2r[64];
        {
            const unsigned long long* wr = reinterpret_cast<const unsigned long long*>(W_hh + (size_t)j * DSq);
#pragma unroll
            for (int i = 0; i < 64; i++) w2r[i] = wr[i];
        }
        if (j < 32) reinterpret_cast<float4*>(hbuf)[j] = reinterpret_cast<const float4*>(state0 + e * DSq)[j];
        const float bhh = b_hh[j];
        float bir = 0.f, biz = 0.f, bin = 0.f;
        if (j < DSq) { bir = b_ih[j]; biz = b_ih[DSq + j]; bin = b_ih[2 * DSq + j]; }
        __syncthreads();

        const ulonglong2* hs2 = reinterpret_cast<const ulonglong2*>(hbuf);

        float qr = 0.f, qz = 0.f, qn = 0.f, rwv = 0.f;
        if (j < DSq) {
            const float* qp = Q + (size_t)(b * Tq) * (3 * DSq);
            qr = qp[j]; qz = qp[DSq + j]; qn = qp[2 * DSq + j];
            rwv = rw[(size_t)(b * Tq) * NEq + e];
        }

        for (int t = 0; t < Tq; t++) {
            const int row = b * Tq + t;
            float nqr = 0.f, nqz = 0.f, nqn = 0.f, nrw = 0.f;
            if (t + 1 < Tq && j < DSq) {
                const float* qp = Q + (size_t)(row + 1) * (3 * DSq);
                nqr = __ldg(qp + j); nqz = __ldg(qp + DSq + j); nqn = __ldg(qp + 2 * DSq + j);
                nrw = __ldg(rw + (size_t)(row + 1) * NEq + e);
            }
            unsigned long long a0 = 0, a1 = 0, a2 = 0, a3 = 0;
#pragma unroll
            for (int i = 0; i < 32; i += 2) {
                ulonglong2 h0 = hs2[i];
                ulonglong2 h1 = hs2[i + 1];
                a0 = fma_f32x2(w2r[i * 2 + 0], h0.x, a0);
                a1 = fma_f32x2(w2r[i * 2 + 1], h0.y, a1);
                a2 = fma_f32x2(w2r[i * 2 + 2], h1.x, a2);
                a3 = fma_f32x2(w2r[i * 2 + 3], h1.y, a3);
            }
            float acc = ((lo_f(a0) + hi_f(a0)) + (lo_f(a1) + hi_f(a1)))
                      + ((lo_f(a2) + hi_f(a2)) + (lo_f(a3) + hi_f(a3)));
            gh[j] = acc + bhh;
            __syncthreads();
            if (j < DSq) {
                float gir = fmaf(rwv, qr, bir);
                float giz = fmaf(rwv, qz, biz);
                float gin = fmaf(rwv, qn, bin);
                float r = __fdividef(1.f, 1.f + __expf(-(gir + gh[j])));
                float z = __fdividef(1.f, 1.f + __expf(-(giz + gh[DSq + j])));
                float xn = fmaf(r, gh[2 * DSq + j], gin);
                float ex = __expf(-2.f * xn);
                float n = __fdividef(1.f - ex, 1.f + ex);
                float hnew = fmaf(z, hbuf[j] - n, n);
                hbuf[j] = hnew;
                size_t idx = (((size_t)row) * NEq + e) * DSq + j;
                // fp32 state_out write moved to the s==0 memory consumer
                __nv_bfloat16 hh = __float2bfloat16(hnew);
                sth[idx] = hh;
                stl[idx] = __float2bfloat16(hnew - __bfloat162float(hh));
            }
            __syncthreads();
            if ((t & 63) == 63 && j == 0) {
                __threadfence();
                atomicAdd(&g_prog[b * 16 + (t >> 6)], 1);
            }
            qr = nqr; qz = nqz; qn = nqn; rwv = nrw;
        }
    } else {
        // ================= CONSUMER GEMM ROLES =================
        __nv_bfloat16* s16 = reinterpret_cast<__nv_bfloat16*>(smem);
        const uint32_t sb = smem_u32(smem);
        const int g = blockIdx.x - 64;
        const int r = g / 10;
        const int s = g - r * 10;

        if (s == 9) {
            // ---------- HEADS tile: 128 rows x 192 cols, K=128 ----------
            const int b = r & 7, tb16 = r >> 3;
            const long long row0 = (long long)b * 8192 + (long long)tb16 * 128;
            const int kflag = b * 16 + (tb16 >> 2);

            if (tid == 0) { while (atomicAdd(&g_prog[kflag], 0) < 8) { } }
            __syncthreads();
            __threadfence();

            const int wid = tid >> 5;
            const int wy = wid & 3;
            const int wx = wid >> 2;

            wmma::fragment<wmma::accumulator, 16, 16, 16, float> acc[2][4];
#pragma unroll
            for (int i = 0; i < 2; i++)
#pragma unroll
                for (int jj = 0; jj < 4; jj++) wmma::fill_fragment(acc[i][jj], 0.0f);

            f_stageA(sb,            sth, row0, 0, DSq, tid);
            f_stageA(sb + F_TA_B,   stl, row0, 0, DSq, tid);
            f_stageB192(sb + H_EBHI * 2, W1h, 0, tid);
            f_stageB192(sb + H_EBLO * 2, W1l, 0, tid);
            CP_COMMIT();

            for (int c = 0; c < 2; c++) {
                if (c == 0) {
                    uint32_t bn = sb + H_BUF_B;
                    f_stageA(bn,            sth, row0, BKT, DSq, tid);
                    f_stageA(bn + F_TA_B,   stl, row0, BKT, DSq, tid);
                    f_stageB192(bn + H_EBHI * 2, W1h, BKT, tid);
                    f_stageB192(bn + H_EBLO * 2, W1l, BKT, tid);
                    CP_COMMIT();
                    CP_WAIT1();
                } else {
                    CP_WAIT0();
                }
                __syncthreads();
                const __nv_bfloat16* base = s16 + (c & 1) * H_EBUF;
#pragma unroll
                for (int ks = 0; ks < BKT; ks += 16) {
                    wmma::fragment<wmma::matrix_b, 16, 16, 16, __nv_bfloat16, wmma::col_major> bh[4], bl[4];
                    wmma::fragment<wmma::matrix_a, 16, 16, 16, __nv_bfloat16, wmma::row_major> ah[2], al[2];
#pragma unroll
                    for (int fn = 0; fn < 4; fn++) {
                        const int nb = wx * 64 + fn * 16;
                        wmma::load_matrix_sync(bh[fn], base + H_EBHI + nb * LDSK + ks, LDSK);
                        wmma::load_matrix_sync(bl[fn], base + H_EBLO + nb * LDSK + ks, LDSK);
                    }
#pragma unroll
                    for (int fm = 0; fm < 2; fm++) {
                        const int mb = wy * 32 + fm * 16;
                        wmma::load_matrix_sync(ah[fm], base + mb * LDSK + ks, LDSK);
                        wmma::load_matrix_sync(al[fm], base + F_EALO + mb * LDSK + ks, LDSK);
                    }
#pragma unroll
                    for (int fm = 0; fm < 2; fm++)
#pragma unroll
                        for (int fn = 0; fn < 4; fn++)
                            wmma::mma_sync(acc[fm][fn], ah[fm], bh[fn], acc[fm][fn]);
#pragma unroll
                    for (int fm = 0; fm < 2; fm++)
#pragma unroll
                        for (int fn = 0; fn < 4; fn++)
                            wmma::mma_sync(acc[fm][fn], ah[fm], bl[fn], acc[fm][fn]);
#pragma unroll
                    for (int fm = 0; fm < 2; fm++)
#pragma unroll
                        for (int fn = 0; fn < 4; fn++)
                            wmma::mma_sync(acc[fm][fn], al[fm], bh[fn], acc[fm][fn]);
                }
                __syncthreads();
            }

            float* Cs = reinterpret_cast<float*>(smem);
#pragma unroll
            for (int fm = 0; fm < 2; fm++)
#pragma unroll
                for (int fn = 0; fn < 4; fn++)
                    wmma::store_matrix_sync(Cs + (wy * 32 + fm * 16) * 192 + wx * 64 + fn * 16,
                                            acc[fm][fn], 192, wmma::mem_row_major);
            __syncthreads();

            {
                const int row = tid & 127;
                const int head = tid >> 7;
                const float* cr = Cs + row * 192 + head * 64;
                float dot = 0.f;
#pragma unroll
                for (int q = 0; q < 16; q++) {
                    int qq = (q + row) & 15;
                    float4 v = *reinterpret_cast<const float4*>(cr + qq * 4);
                    int col = head * 64 + qq * 4;
                    dot = fmaf(gelu_exact(v.x + __ldg(b1cat + col + 0)), __ldg(W2cat + col + 0), dot);
                    dot = fmaf(gelu_exact(v.y + __ldg(b1cat + col + 1)), __ldg(W2cat + col + 1), dot);
                    dot = fmaf(gelu_exact(v.z + __ldg(b1cat + col + 2)), __ldg(W2cat + col + 2), dot);
                    dot = fmaf(gelu_exact(v.w + __ldg(b1cat + col + 3)), __ldg(W2cat + col + 3), dot);
                }
                float* op = (head == 0) ? oH : (head == 1) ? oT : oV;
                float b2 = (head == 0) ? __ldg(bh2) : (head == 1) ? __ldg(bt2) : __ldg(bv2);
                op[row0 + row] = dot + b2;
            }
            return;
        }

        // ---------- MEMORY / POOLED tiles ----------
        const __nv_bfloat16 *Bhi, *Blo;
        const float* biasv;
        float* Cp;
        long long row0;
        int lda, ldb, n0, nCh, kflag;

        if (s < 8) {
            const int b = r & 7, tb16 = r >> 3;
            row0 = (long long)b * 8192 + (long long)tb16 * 128;
            lda = DSq; ldb = DSq; nCh = 2;
            Bhi = Wmh; Blo = Wml;
            n0 = s * 96; biasv = bm; Cp = Cmem;
            kflag = b * 16 + (tb16 >> 2);
        } else {
            const int rowtile = r >> 3;
            const int tb16 = rowtile >> 3, b = rowtile & 7;
            row0 = (long long)b * 1024 + (long long)tb16 * 128;
            lda = NEq * DSq; ldb = NEq * DSq; nCh = 16;
            Bhi = Mch; Blo = Mcl;
            n0 = (r & 7) * 96; biasv = pbias; Cp = Cpool;
            kflag = b * 16 + 2 * tb16 + 1;
        }

        if (tid == 0) { while (atomicAdd(&g_prog[kflag], 0) < 8) { } }
        __syncthreads();
        __threadfence();

        f_gemm96(smem, sb, tid, sth, stl, row0, lda, Bhi, Blo, n0, ldb,
                 nCh, biasv, Cp, row0, Dq);

        // s==0 memory tile also reconstructs fp32 state_out for its 128 rows
        if (s == 0) {
#pragma unroll
            for (int it = 0; it < 11; it++) {
                int u = it * 384 + tid;             // 4096 float4 units
                if (u < 4096) {
                    int row = u >> 5, q = u & 31;
                    size_t idx = (size_t)(row0 + row) * DSq + q * 4;
                    __nv_bfloat162 h0 = *reinterpret_cast<const __nv_bfloat162*>(sth + idx);
                    __nv_bfloat162 h1 = *reinterpret_cast<const __nv_bfloat162*>(sth + idx + 2);
                    __nv_bfloat162 l0 = *reinterpret_cast<const __nv_bfloat162*>(stl + idx);
                    __nv_bfloat162 l1 = *reinterpret_cast<const __nv_bfloat162*>(stl + idx + 2);
                    float4 v;
                    v.x = __bfloat162float(h0.x) + __bfloat162float(l0.x);
                    v.y = __bfloat162float(h0.y) + __bfloat162float(l0.y);
                    v.z = __bfloat162float(h1.x) + __bfloat162float(l1.x);
                    v.w = __bfloat162float(h1.y) + __bfloat162float(l1.y);
                    *reinterpret_cast<float4*>(state_out + idx) = v;
                }
            }
        }
    }
}

// ---------------------------------------------------------------------------
// MERGED prep + route(+cvt) + pbias
// ---------------------------------------------------------------------------
#define PREP_TOTAL (DSq*Dq + 3*DSq*DSq + Dq*DSq + Dq*DSq + 256*DSq + 256 + (long long)Dq*NEq*Dq)
#define PREP_B     ((int)((PREP_TOTAL + 255) / 256))

__global__ __launch_bounds__(256)
void prep_all(const float* __restrict__ Wi, const float* __restrict__ W_ih,
              const float* __restrict__ Wm, const float* __restrict__ Ws,
              const float* __restrict__ Wh1, const float* __restrict__ Wt1,
              const float* __restrict__ Wv1,
              const float* __restrict__ bh1, const float* __restrict__ bt1,
              const float* __restrict__ bv1,
              const float* __restrict__ Wh2, const float* __restrict__ Wt2,
              const float* __restrict__ Wv2,
              const float* __restrict__ h_seq, const float* __restrict__ ek,
              float* __restrict__ rwout,
              __nv_bfloat16* __restrict__ hsh, __nv_bfloat16* __restrict__ hsl,
              const float* __restrict__ bm, const float* __restrict__ bs,
              float* __restrict__ pb)
{
    const int bid = blockIdx.x;
    if (bid < PREP_B) {
        if (bid == 0 && threadIdx.x < 128) g_prog[threadIdx.x] = 0;
        const int N_Wi = DSq * Dq, N_Wih = 3 * DSq * DSq, N_Wm = Dq * DSq;
        const int N_W1 = 256 * DSq;
        const long long N_Ws = (long long)Dq * NEq * Dq;
        long long idx = (long long)bid * 256 + threadIdx.x;
        __nv_bfloat16 h, l;
        if (idx < N_Wi)  { hilo(Wi[idx], h, l);   g_Wi_hi[idx] = h;  g_Wi_lo[idx] = l;  return; }
        idx -= N_Wi;
        if (idx < N_Wih) { hilo(W_ih[idx], h, l); g_Wih_hi[idx] = h; g_Wih_lo[idx] = l; return; }
        idx -= N_Wih;
        if (idx < N_Wm)  { hilo(Wm[idx], h, l);   g_Wm_hi[idx] = h;  g_Wm_lo[idx] = l;  return; }
        idx -= N_Wm;
        if (idx < N_Wm) {
            int j = (int)(idx / DSq), k = (int)(idx % DSq);
            hilo(Wm[idx], h, l);
            g_WmT_hi[(size_t)k * Dq + j] = h; g_WmT_lo[(size_t)k * Dq + j] = l; return;
        }
        idx -= N_Wm;
        if (idx < N_W1) {
            int r = (int)(idx / DSq), c = (int)(idx % DSq);
            float v = (r < 64) ? Wh1[r * DSq + c] : (r < 128) ? Wt1[(r - 64) * DSq + c]
                    : (r < 192) ? Wv1[(r - 128) * DSq + c] : 0.f;
            hilo(v, h, l); g_W1_hi[idx] = h; g_W1_lo[idx] = l; return;
        }
        idx -= N_W1;
        if (idx < 256) {
            int i = (int)idx;
            g_b1cat[i] = (i < 64) ? bh1[i] : (i < 128) ? bt1[i - 64] : (i < 192) ? bv1[i - 128] : 0.f;
            g_W2cat[i] = (i < 64) ? Wh2[i] : (i < 128) ? Wt2[i - 64] : (i < 192) ? Wv2[i - 128] : 0.f;
            return;
        }
        idx -= 256;
        if (idx < N_Ws) { hilo(Ws[idx], h, l); g_Ws_hi[idx] = h; g_Ws_lo[idx] = l; }
        return;
    }
    if (bid < PREP_B + ROWS) {
        const int row = bid - PREP_B;
        const int w = threadIdx.x >> 5, lane = threadIdx.x & 31;
        const float* hr = h_seq + (size_t)row * Dq;
        const float* er = ek + (size_t)w * Dq;
        float s = 0.f;
#pragma unroll 4
        for (int k = lane; k < Dq; k += 32) s = fmaf(hr[k], er[k], s);
#pragma unroll
        for (int o = 16; o; o >>= 1) s += __shfl_xor_sync(0xffffffffu, s, o);
        __shared__ float lg[NEq];
        if (lane == 0) lg[w] = s;
#pragma unroll
        for (int i = threadIdx.x; i < Dq; i += 256) {
            __nv_bfloat16 h, l; hilo(hr[i], h, l);
            hsh[(size_t)row * Dq + i] = h;
            hsl[(size_t)row * Dq + i] = l;
        }
        __syncthreads();
        if (threadIdx.x == 0) {
            const float inv = 0.036084391824351615f;
            float v[NEq], m = -1e30f;
#pragma unroll
            for (int e = 0; e < NEq; e++) { v[e] = lg[e] * inv; m = fmaxf(m, v[e]); }
            float den = 0.f;
#pragma unroll
            for (int e = 0; e < NEq; e++) { v[e] = __expf(v[e] - m); den += v[e]; }
            float id = 1.f / den;
#pragma unroll
            for (int e = 0; e < NEq; e++) rwout[(size_t)row * NEq + e] = v[e] * id;
        }
        return;
    }
    {
        const int d = bid - PREP_B - ROWS;
        const int tid = threadIdx.x;
        float s = 0.f;
        int jm = tid;                         // running j % Dq (no modulo)
        for (int j = tid; j < NEq * Dq; j += 256) {
            s = fmaf(bm[jm], Ws[(size_t)d * (NEq * Dq) + j], s);
            jm += 256; if (jm >= Dq) jm -= Dq;
        }
        __shared__ float red[256];
        red[tid] = s; __syncthreads();
        for (int o = 128; o; o >>= 1) { if (tid < o) red[tid] += red[tid + o]; __syncthreads(); }
        if (tid == 0) pb[d] = red[0] + bs[d];
    }
}

// ---------------------------------------------------------------------------
// Launch
// ---------------------------------------------------------------------------
extern "C" void kernel_launch(void* const* d_in, const int* in_sizes, int n_in,
                              void* d_out, int out_size)
{
    const float* h_seq = (const float*)d_in[0];
    const float* ek    = (const float*)d_in[1];
    const float* state0= (const float*)d_in[2];
    const float* Wi    = (const float*)d_in[3];
    const float* bi    = (const float*)d_in[4];
    const float* W_ih  = (const float*)d_in[5];
    const float* W_hh  = (const float*)d_in[6];
    const float* b_ih  = (const float*)d_in[7];
    const float* b_hh  = (const float*)d_in[8];
    const float* Wm    = (const float*)d_in[9];
    const float* bm    = (const float*)d_in[10];
    const float* Ws    = (const float*)d_in[11];
    const float* bs    = (const float*)d_in[12];
    const float* Wh1   = (const float*)d_in[13];
    const float* bh1   = (const float*)d_in[14];
    const float* Wh2   = (const float*)d_in[15];
    const float* bh2   = (const float*)d_in[16];
    const float* Wt1   = (const float*)d_in[17];
    const float* bt1   = (const float*)d_in[18];
    const float* Wt2   = (const float*)d_in[19];
    const float* bt2   = (const float*)d_in[20];
    const float* Wv1   = (const float*)d_in[21];
    const float* bv1   = (const float*)d_in[22];
    const float* Wv2   = (const float*)d_in[23];
    const float* bv2   = (const float*)d_in[24];
    float* out = (float*)d_out;

    cudaFuncSetAttribute(gemm_tc, cudaFuncAttributeMaxDynamicSharedMemorySize, SM_BYTES);
    cudaFuncSetAttribute(gemm_proj_mc, cudaFuncAttributeMaxDynamicSharedMemorySize, SM_BYTES);
    cudaFuncSetAttribute(fused_scan_mem, cudaFuncAttributeMaxDynamicSharedMemorySize, F_SM);

#define SYMF(p, s) float* p; cudaGetSymbolAddress((void**)&p, s)
#define SYMB(p, s) __nv_bfloat16* p; cudaGetSymbolAddress((void**)&p, s)
    SYMB(p_hsh, g_hseq_hi);  SYMB(p_hsl, g_hseq_lo);
    SYMB(p_sth, g_state_hi); SYMB(p_stl, g_state_lo);
    SYMB(p_prh, g_projh);    SYMB(p_prl, g_projl);
    SYMB(p_wsh, g_Ws_hi);    SYMB(p_wsl, g_Ws_lo);
    SYMB(p_wih, g_Wi_hi);    SYMB(p_wil, g_Wi_lo);
    SYMB(p_whh, g_Wih_hi);   SYMB(p_whl, g_Wih_lo);
    SYMB(p_wmh, g_Wm_hi);    SYMB(p_wml, g_Wm_lo);
    SYMB(p_wth, g_WmT_hi);   SYMB(p_wtl, g_WmT_lo);
    SYMB(p_mch, g_Mc_hi);    SYMB(p_mcl, g_Mc_lo);
    SYMB(p_w1h, g_W1_hi);    SYMB(p_w1l, g_W1_lo);
    SYMF(p_Q, g_Q); SYMF(p_pb, g_pbias);
    SYMF(p_b1, g_b1cat);  SYMF(p_w2, g_W2cat);

    // 1) MERGED prep + route + pbias (+flag reset)
    prep_all<<<PREP_B + ROWS + Dq, 256>>>(Wi, W_ih, Wm, Ws, Wh1, Wt1, Wv1,
                                          bh1, bt1, bv1, Wh2, Wt2, Wv2,
                                          h_seq, ek, out + RW_OFF, p_hsh, p_hsl,
                                          bm, bs, p_pb);

    // 2) MERGED proj + Mc (112 blocks)
    gemm_proj_mc<<<112, 512, SM_BYTES>>>(p_hsh, p_hsl, p_wih, p_wil, bi,
                                         p_prh, p_prl,
                                         p_wsh, p_wsl, p_wth, p_wtl,
                                         p_mch, p_mcl);

    // 3) Q = proj @ W_ih^T  [8192,384] K=128
    gemm_tc<<<dim3(3, ROWS / 128), 512, SM_BYTES>>>(p_prh, p_prl, DSq,
                                                    p_whh, p_whl, DSq,
                                                    p_Q, 3 * DSq, DSq / BKT);

    // 4) FUSED: scan (64) + memory/pooled/heads consumers (5120)
    fused_scan_mem<<<64 + 5120, 384, F_SM>>>(p_Q, out + RW_OFF, state0, W_hh, b_ih, b_hh,
                                             out + STATE_OFF, p_sth, p_stl,
                                             p_wmh, p_wml, bm, out + MEM_OFF,
                                             p_mch, p_mcl, p_pb, out + POOLED_OFF,
                                             p_w1h, p_w1l, p_b1, p_w2, bh2, bt2, bv2,
                                             out + HOLDER_OFF, out + TAGGED_OFF, out + VISIBLE_OFF);

    (void)in_sizes; (void)n_in; (void)out_size;
}